// round 3
// baseline (speedup 1.0000x reference)
#include <cuda_runtime.h>
#include <math.h>

#define B_  32
#define M_  64
#define Kk_ 36
#define DS_ 512
#define DX_ 128
#define DQ_ 512
#define H_  256
#define ROWS_S 2048
#define ROWS_X 1152

// Scratch (allocation-free rule: __device__ globals)
__device__ __align__(16) float g_preq[B_*H_];        // 32*256
__device__ __align__(16) float g_C[ROWS_S*512];      // [2048,512]: 0:256 pre_s, 256:512 h1
__device__ __align__(16) float g_hs[ROWS_S*DX_];     // 2048*128
__device__ __align__(16) float g_base[ROWS_X*H_];    // 1152*256

// Packed dual-FMA (sm_103a): d = a*b + d elementwise on float2
__device__ __forceinline__ void fma2(float2 &d, const float2 &a, const float2 &b) {
    asm("fma.rn.f32x2 %0, %1, %2, %0;"
        : "+l"(reinterpret_cast<unsigned long long&>(d))
        : "l"(reinterpret_cast<const unsigned long long&>(a)),
          "l"(reinterpret_cast<const unsigned long long&>(b)));
}

// ---------------------------------------------------------------------------
// L1: bx<128 : C[2048,512] = [ s2@w_s | relu(s2@hw1+hb1) ]
//     128x64 block tile, BK=16, 128 threads, 8x8 microtile, double-buffered.
//     bx>=128: preq[b] = q[b] @ w_q  (32 lean blocks)
// ---------------------------------------------------------------------------
__global__ void __launch_bounds__(128) k1(
    const float* __restrict__ s2, const float* __restrict__ w1,
    const float* __restrict__ hw1, const float* __restrict__ hb1,
    const float* __restrict__ q, float* __restrict__ C,
    float* __restrict__ preq)
{
    __shared__ float As[2][16][132];
    __shared__ float Bs[2][16][64];
    const int tid = threadIdx.x;
    const int bx  = blockIdx.x;

    if (bx >= 128) {  // ---- pre_q: h-pair (2*tid, 2*tid+1) per thread ----
        float* qs = &As[0][0][0];             // 512 floats scratch
        const int b = bx - 128;
        for (int d = tid; d < DQ_; d += 128) qs[d] = q[b*DQ_ + d];
        __syncthreads();
        const float* wq = w1 + (size_t)(DS_ + DX_) * H_ + tid * 2;
        float2 acc = make_float2(0.f, 0.f);
        #pragma unroll 8
        for (int d = 0; d < DQ_; d++) {
            float2 wv = *reinterpret_cast<const float2*>(wq + (size_t)d * H_);
            float2 qd = make_float2(qs[d], qs[d]);
            fma2(acc, qd, wv);
        }
        *reinterpret_cast<float2*>(&preq[b*H_ + tid*2]) = acc;
        return;
    }

    const int bm = bx >> 3, bn = bx & 7;
    const int m0 = bm * 128, n0 = bn * 64;
    const float* Bp; bool relu; int bcol;
    if (n0 < 256) { Bp = w1;  bcol = n0;       relu = false; }
    else          { Bp = hw1; bcol = n0 - 256; relu = true;  }

    const int mo = (tid >> 3) * 8;           // 0..120
    const int no = (tid & 7) * 8;            // 0..56

    const float* Ag = s2 + (size_t)(m0 + tid) * DS_;
    const int bkr = tid >> 3;                // 0..15
    const int bc4 = (tid & 7) * 4;           // 0..28
    const float* Bg = Bp + (size_t)bkr * H_ + bcol + bc4;

    float2 acc[4][8];
    #pragma unroll
    for (int i = 0; i < 4; i++)
        #pragma unroll
        for (int j = 0; j < 8; j++) acc[i][j] = make_float2(0.f, 0.f);

    float4 av[4], bv0, bv1;
    #pragma unroll
    for (int i = 0; i < 4; i++)
        av[i] = *reinterpret_cast<const float4*>(Ag + i * 4);
    bv0 = *reinterpret_cast<const float4*>(Bg);
    bv1 = *reinterpret_cast<const float4*>(Bg + 32);

    #pragma unroll
    for (int i = 0; i < 4; i++) {
        As[0][i*4+0][tid] = av[i].x; As[0][i*4+1][tid] = av[i].y;
        As[0][i*4+2][tid] = av[i].z; As[0][i*4+3][tid] = av[i].w;
    }
    *reinterpret_cast<float4*>(&Bs[0][bkr][bc4])      = bv0;
    *reinterpret_cast<float4*>(&Bs[0][bkr][bc4 + 32]) = bv1;
    __syncthreads();

    #pragma unroll 1
    for (int kt = 0; kt < 32; kt++) {
        const int buf = kt & 1;
        if (kt < 31) {
            const float* Agk = Ag + (kt + 1) * 16;
            #pragma unroll
            for (int i = 0; i < 4; i++)
                av[i] = *reinterpret_cast<const float4*>(Agk + i * 4);
            const float* Bgk = Bg + (size_t)(kt + 1) * 16 * H_;
            bv0 = *reinterpret_cast<const float4*>(Bgk);
            bv1 = *reinterpret_cast<const float4*>(Bgk + 32);
        }
        #pragma unroll
        for (int kk = 0; kk < 16; kk++) {
            float4 a0 = *reinterpret_cast<const float4*>(&As[buf][kk][mo]);
            float4 a1 = *reinterpret_cast<const float4*>(&As[buf][kk][mo + 4]);
            float4 b0 = *reinterpret_cast<const float4*>(&Bs[buf][kk][no]);
            float4 b1 = *reinterpret_cast<const float4*>(&Bs[buf][kk][no + 4]);
            float2 am[4] = {{a0.x,a0.y},{a0.z,a0.w},{a1.x,a1.y},{a1.z,a1.w}};
            float  bb[8] = {b0.x,b0.y,b0.z,b0.w,b1.x,b1.y,b1.z,b1.w};
            #pragma unroll
            for (int i = 0; i < 4; i++)
                #pragma unroll
                for (int j = 0; j < 8; j++)
                    fma2(acc[i][j], am[i], make_float2(bb[j], bb[j]));
        }
        if (kt < 31) {
            const int nb = buf ^ 1;
            #pragma unroll
            for (int i = 0; i < 4; i++) {
                As[nb][i*4+0][tid] = av[i].x; As[nb][i*4+1][tid] = av[i].y;
                As[nb][i*4+2][tid] = av[i].z; As[nb][i*4+3][tid] = av[i].w;
            }
            *reinterpret_cast<float4*>(&Bs[nb][bkr][bc4])      = bv0;
            *reinterpret_cast<float4*>(&Bs[nb][bkr][bc4 + 32]) = bv1;
        }
        __syncthreads();
    }

    float bb[8] = {0,0,0,0,0,0,0,0};
    if (relu) {
        float4 t0 = *reinterpret_cast<const float4*>(&hb1[bcol + no]);
        float4 t1 = *reinterpret_cast<const float4*>(&hb1[bcol + no + 4]);
        bb[0]=t0.x; bb[1]=t0.y; bb[2]=t0.z; bb[3]=t0.w;
        bb[4]=t1.x; bb[5]=t1.y; bb[6]=t1.z; bb[7]=t1.w;
    }
    #pragma unroll
    for (int i = 0; i < 4; i++) {
        const int r0 = m0 + mo + 2*i;
        float4 lo0 = make_float4(acc[i][0].x, acc[i][1].x, acc[i][2].x, acc[i][3].x);
        float4 lo1 = make_float4(acc[i][4].x, acc[i][5].x, acc[i][6].x, acc[i][7].x);
        float4 hi0 = make_float4(acc[i][0].y, acc[i][1].y, acc[i][2].y, acc[i][3].y);
        float4 hi1 = make_float4(acc[i][4].y, acc[i][5].y, acc[i][6].y, acc[i][7].y);
        if (relu) {
            lo0.x=fmaxf(lo0.x+bb[0],0.f); lo0.y=fmaxf(lo0.y+bb[1],0.f);
            lo0.z=fmaxf(lo0.z+bb[2],0.f); lo0.w=fmaxf(lo0.w+bb[3],0.f);
            lo1.x=fmaxf(lo1.x+bb[4],0.f); lo1.y=fmaxf(lo1.y+bb[5],0.f);
            lo1.z=fmaxf(lo1.z+bb[6],0.f); lo1.w=fmaxf(lo1.w+bb[7],0.f);
            hi0.x=fmaxf(hi0.x+bb[0],0.f); hi0.y=fmaxf(hi0.y+bb[1],0.f);
            hi0.z=fmaxf(hi0.z+bb[2],0.f); hi0.w=fmaxf(hi0.w+bb[3],0.f);
            hi1.x=fmaxf(hi1.x+bb[4],0.f); hi1.y=fmaxf(hi1.y+bb[5],0.f);
            hi1.z=fmaxf(hi1.z+bb[6],0.f); hi1.w=fmaxf(hi1.w+bb[7],0.f);
        }
        float* Cr = C + (size_t)r0 * 512 + n0 + no;
        *reinterpret_cast<float4*>(Cr)           = lo0;
        *reinterpret_cast<float4*>(Cr + 4)       = lo1;
        *reinterpret_cast<float4*>(Cr + 512)     = hi0;
        *reinterpret_cast<float4*>(Cr + 512 + 4) = hi1;
    }
}

// ---------------------------------------------------------------------------
// L2: bx<64 : hs[2048,128] = h1 @ hw2 + hb2      (64x64 tiles, K=256)
//     bx>=64: base[1152,256] = x0@w_x + preq[row/36] + b1  (64x64, K=128)
//     256 thr, double-buffered.
// ---------------------------------------------------------------------------
__global__ void __launch_bounds__(256) k2(
    const float* __restrict__ C, const float* __restrict__ hw2,
    const float* __restrict__ hb2, const float* __restrict__ x0,
    const float* __restrict__ w1, const float* __restrict__ b1,
    const float* __restrict__ preq,
    float* __restrict__ hs, float* __restrict__ base)
{
    __shared__ float As[2][16][68];
    __shared__ float Bs[2][16][64];
    const int tid = threadIdx.x;
    const int bx  = blockIdx.x;

    const float* A; const float* Bp; int lda, ldb, nt, m0, n0, mode;
    if (bx < 64) {
        mode = 0; const int tm = bx >> 1, tn = bx & 1;
        m0 = tm*64; n0 = tn*64;
        A = C + 256; lda = 512; Bp = hw2; ldb = 128; nt = 256/16;
    } else {
        mode = 1; const int bb = bx - 64; const int tm = bb >> 2, tn = bb & 3;
        m0 = tm*64; n0 = tn*64;
        A = x0; lda = 128; Bp = w1 + (size_t)DS_*H_; ldb = 256; nt = 128/16;
    }

    const int tx = tid & 15, ty = tid >> 4;
    const int ar = tid >> 2;
    const int ac = (tid & 3) << 2;
    const int bkr = tid >> 4;
    const int bn4 = (tid & 15) << 2;

    const float* Ag = A  + (size_t)(m0 + ar) * lda + ac;
    const float* Bg = Bp + (size_t)bkr * ldb + n0 + bn4;

    float2 acc[2][4];
    #pragma unroll
    for (int i = 0; i < 2; i++)
        #pragma unroll
        for (int j = 0; j < 4; j++) acc[i][j] = make_float2(0.f, 0.f);

    float4 av = *reinterpret_cast<const float4*>(Ag);
    float4 bv = *reinterpret_cast<const float4*>(Bg);
    As[0][ac+0][ar] = av.x; As[0][ac+1][ar] = av.y;
    As[0][ac+2][ar] = av.z; As[0][ac+3][ar] = av.w;
    *reinterpret_cast<float4*>(&Bs[0][bkr][bn4]) = bv;
    __syncthreads();

    #pragma unroll 1
    for (int kt = 0; kt < nt; kt++) {
        const int buf = kt & 1;
        if (kt + 1 < nt) {
            av = *reinterpret_cast<const float4*>(Ag + (kt+1)*16);
            bv = *reinterpret_cast<const float4*>(Bg + (size_t)(kt+1)*16*ldb);
        }
        #pragma unroll
        for (int kk = 0; kk < 16; kk++) {
            float4 a4 = *reinterpret_cast<const float4*>(&As[buf][kk][ty*4]);
            float4 b4 = *reinterpret_cast<const float4*>(&Bs[buf][kk][tx*4]);
            float2 a2v[2] = {{a4.x,a4.y},{a4.z,a4.w}};
            float2 bd[4]  = {{b4.x,b4.x},{b4.y,b4.y},{b4.z,b4.z},{b4.w,b4.w}};
            #pragma unroll
            for (int i = 0; i < 2; i++)
                #pragma unroll
                for (int j = 0; j < 4; j++)
                    fma2(acc[i][j], a2v[i], bd[j]);
        }
        if (kt + 1 < nt) {
            const int nb = buf ^ 1;
            As[nb][ac+0][ar] = av.x; As[nb][ac+1][ar] = av.y;
            As[nb][ac+2][ar] = av.z; As[nb][ac+3][ar] = av.w;
            *reinterpret_cast<float4*>(&Bs[nb][bkr][bn4]) = bv;
        }
        __syncthreads();
    }

    if (mode == 0) {
        float4 bb = *reinterpret_cast<const float4*>(&hb2[n0 + tx*4]);
        float* Or = hs + (size_t)(m0 + ty*4) * DX_ + n0 + tx*4;
        #pragma unroll
        for (int i = 0; i < 2; i++) {
            float4 lo = make_float4(acc[i][0].x+bb.x, acc[i][1].x+bb.y, acc[i][2].x+bb.z, acc[i][3].x+bb.w);
            float4 hi = make_float4(acc[i][0].y+bb.x, acc[i][1].y+bb.y, acc[i][2].y+bb.z, acc[i][3].y+bb.w);
            *reinterpret_cast<float4*>(Or + (size_t)(2*i  )*DX_) = lo;
            *reinterpret_cast<float4*>(Or + (size_t)(2*i+1)*DX_) = hi;
        }
    } else {
        float4 bb = *reinterpret_cast<const float4*>(&b1[n0 + tx*4]);
        #pragma unroll
        for (int i = 0; i < 2; i++) {
            const int r0 = m0 + ty*4 + 2*i;
            float4 p0 = *reinterpret_cast<const float4*>(&preq[(r0   /Kk_)*H_ + n0 + tx*4]);
            float4 p1 = *reinterpret_cast<const float4*>(&preq[((r0+1)/Kk_)*H_ + n0 + tx*4]);
            float4 lo = make_float4(acc[i][0].x+bb.x+p0.x, acc[i][1].x+bb.y+p0.y,
                                    acc[i][2].x+bb.z+p0.z, acc[i][3].x+bb.w+p0.w);
            float4 hi = make_float4(acc[i][0].y+bb.x+p1.x, acc[i][1].y+bb.y+p1.y,
                                    acc[i][2].y+bb.z+p1.z, acc[i][3].y+bb.w+p1.w);
            *reinterpret_cast<float4*>(&base[(size_t)(r0  )*H_ + n0 + tx*4]) = lo;
            *reinterpret_cast<float4*>(&base[(size_t)(r0+1)*H_ + n0 + tx*4]) = hi;
        }
    }
}

// ---------------------------------------------------------------------------
// L3: fused logits + softmax + aggregation + x0 copy. 4 k per block.
// ---------------------------------------------------------------------------
__global__ void __launch_bounds__(256) att_k(
    const float* __restrict__ Cmat, const float* __restrict__ base,
    const float* __restrict__ hsm, const float* __restrict__ w2,
    const float* __restrict__ x0, float* __restrict__ out)
{
    const int b  = blockIdx.x / 9;
    const int kg = blockIdx.x % 9;
    const int bk0 = b * Kk_ + kg * 4;
    const int tid = threadIdx.x;
    const int warp = tid >> 5, lane = tid & 31;

    __shared__ float base_s[4][H_];
    __shared__ float w2s[H_];
    __shared__ float lgt[4][M_];
    __shared__ float ew[4][M_];
    __shared__ float sinv[4];

    for (int idx = tid; idx < 4*H_; idx += 256)
        base_s[idx >> 8][idx & 255] = base[(size_t)(bk0 + (idx >> 8)) * H_ + (idx & 255)];
    w2s[tid] = w2[tid];
    __syncthreads();

    const float* pres = Cmat + (size_t)(b * M_) * 512;
    #pragma unroll
    for (int mi = 0; mi < 8; mi++) {
        const int m = warp * 8 + mi;
        const float* row = pres + (size_t)m * 512;
        float r[8];
        #pragma unroll
        for (int j = 0; j < 8; j++) r[j] = row[lane + 32*j];
        #pragma unroll
        for (int k = 0; k < 4; k++) {
            float acc = 0.f;
            #pragma unroll
            for (int j = 0; j < 8; j++) {
                const int h = lane + 32*j;
                acc = fmaf(fmaxf(r[j] + base_s[k][h], 0.f), w2s[h], acc);
            }
            #pragma unroll
            for (int off = 16; off; off >>= 1)
                acc += __shfl_xor_sync(0xffffffffu, acc, off);
            if (lane == 0) lgt[k][m] = acc;
        }
    }
    __syncthreads();

    if (warp < 4) {
        const int k = warp;
        float l0 = lgt[k][lane], l1 = lgt[k][lane + 32];
        float mx = fmaxf(l0, l1);
        #pragma unroll
        for (int off = 16; off; off >>= 1)
            mx = fmaxf(mx, __shfl_xor_sync(0xffffffffu, mx, off));
        float e0 = expf(l0 - mx), e1 = expf(l1 - mx);
        float s = e0 + e1;
        #pragma unroll
        for (int off = 16; off; off >>= 1)
            s += __shfl_xor_sync(0xffffffffu, s, off);
        ew[k][lane] = e0; ew[k][lane + 32] = e1;
        if (lane == 0) sinv[k] = 1.f / s;
    }
    __syncthreads();

    {
        const int f  = tid & 127;
        const int kp = tid >> 7;
        const int k0 = kp * 2, k1 = k0 + 1;
        const float* hb = hsm + (size_t)(b * M_) * DX_ + f;
        float a0 = 0.f, a1 = 0.f;
        #pragma unroll 8
        for (int m = 0; m < M_; m++) {
            const float v = hb[(size_t)m * DX_];
            a0 = fmaf(ew[k0][m], v, a0);
            a1 = fmaf(ew[k1][m], v, a1);
        }
        out[(size_t)(bk0 + k0) * 256 + 128 + f] = a0 * sinv[k0];
        out[(size_t)(bk0 + k1) * 256 + 128 + f] = a1 * sinv[k1];
    }
    for (int idx = tid; idx < 4 * DX_; idx += 256) {
        const int k = idx >> 7, f = idx & 127;
        out[(size_t)(bk0 + k) * 256 + f] = x0[(size_t)(bk0 + k) * DX_ + f];
    }
}

// ---------------------------------------------------------------------------
extern "C" void kernel_launch(void* const* d_in, const int* in_sizes, int n_in,
                              void* d_out, int out_size)
{
    (void)in_sizes; (void)n_in; (void)out_size;
    const float* s2  = (const float*)d_in[0];
    const float* x0  = (const float*)d_in[1];
    const float* q   = (const float*)d_in[2];
    const float* w1  = (const float*)d_in[3];
    const float* b1  = (const float*)d_in[4];
    const float* w2  = (const float*)d_in[5];
    const float* hw1 = (const float*)d_in[7];
    const float* hb1 = (const float*)d_in[8];
    const float* hw2 = (const float*)d_in[9];
    const float* hb2 = (const float*)d_in[10];
    float* out = (float*)d_out;

    float *preq, *C, *hs, *base;
    cudaGetSymbolAddress((void**)&preq, g_preq);
    cudaGetSymbolAddress((void**)&C,    g_C);
    cudaGetSymbolAddress((void**)&hs,   g_hs);
    cudaGetSymbolAddress((void**)&base, g_base);

    k1<<<160, 128>>>(s2, w1, hw1, hb1, q, C, preq);
    k2<<<136, 256>>>(C, hw2, hb2, x0, w1, b1, preq, hs, base);
    att_k<<<288, 256>>>(C, base, hs, w2, x0, out);
}

// round 4
// speedup vs baseline: 1.0971x; 1.0971x over previous
#include <cuda_runtime.h>
#include <math.h>

#define B_  32
#define M_  64
#define Kk_ 36
#define DS_ 512
#define DX_ 128
#define DQ_ 512
#define H_  256
#define ROWS_S 2048
#define ROWS_X 1152

// Scratch (allocation-free rule: __device__ globals)
__device__ __align__(16) float g_preq[B_*H_];
__device__ __align__(16) float g_C[ROWS_S*512];      // 0:256 pre_s, 256:512 h1
__device__ __align__(16) float g_hs[ROWS_S*DX_];
__device__ __align__(16) float g_base[ROWS_X*H_];

// Packed dual-FMA (sm_103a): d = a*b + d elementwise on float2
__device__ __forceinline__ void fma2(float2 &d, const float2 &a, const float2 &b) {
    asm("fma.rn.f32x2 %0, %1, %2, %0;"
        : "+l"(reinterpret_cast<unsigned long long&>(d))
        : "l"(reinterpret_cast<const unsigned long long&>(a)),
          "l"(reinterpret_cast<const unsigned long long&>(b)));
}

// ---------------------------------------------------------------------------
// L1: bx<256 : C[2048,512] = [ s2@w_s | relu(s2@hw1+hb1) ]
//     64x64 block tile, BK=16, 128 threads, 8x4 microtile, double-buffered.
//     grid 288 => ~2 co-resident blocks/SM (independent barrier domains).
//     bx>=256: preq[b] = q[b] @ w_q  (32 lean blocks)
// ---------------------------------------------------------------------------
__global__ void __launch_bounds__(128) k1(
    const float* __restrict__ s2, const float* __restrict__ w1,
    const float* __restrict__ hw1, const float* __restrict__ hb1,
    const float* __restrict__ q, float* __restrict__ C,
    float* __restrict__ preq)
{
    __shared__ float As[2][16][68];
    __shared__ float Bs[2][16][64];
    const int tid = threadIdx.x;
    const int bx  = blockIdx.x;

    if (bx >= 256) {  // ---- pre_q: h-pair (2*tid, 2*tid+1) per thread ----
        float* qs = &As[0][0][0];
        const int b = bx - 256;
        for (int d = tid; d < DQ_; d += 128) qs[d] = q[b*DQ_ + d];
        __syncthreads();
        const float* wq = w1 + (size_t)(DS_ + DX_) * H_ + tid * 2;
        float2 acc = make_float2(0.f, 0.f);
        #pragma unroll 8
        for (int d = 0; d < DQ_; d++) {
            float2 wv = *reinterpret_cast<const float2*>(wq + (size_t)d * H_);
            fma2(acc, make_float2(qs[d], qs[d]), wv);
        }
        *reinterpret_cast<float2*>(&preq[b*H_ + tid*2]) = acc;
        return;
    }

    const int bm = bx >> 3, bn = bx & 7;
    const int m0 = bm * 64, n0 = bn * 64;
    const float* Bp; bool relu; int bcol;
    if (n0 < 256) { Bp = w1;  bcol = n0;       relu = false; }
    else          { Bp = hw1; bcol = n0 - 256; relu = true;  }

    const int tx = tid & 15, ty = tid >> 4;   // 16 x 8
    const int mo = ty * 8;                    // 0..56
    const int no = tx * 4;                    // 0..60

    // A loader: row = tid&63, cb = (tid>>6)*8  (64 rows x 16 k)
    const int arow = tid & 63;
    const int acb  = (tid >> 6) * 8;
    const float* Ag = s2 + (size_t)(m0 + arow) * DS_ + acb;
    // B loader: row = tid>>3 (0..15), col = (tid&7)*8
    const int brow = tid >> 3;
    const int bco  = (tid & 7) * 8;
    const float* Bg = Bp + (size_t)brow * H_ + bcol + bco;

    float2 acc[4][4];
    #pragma unroll
    for (int i = 0; i < 4; i++)
        #pragma unroll
        for (int j = 0; j < 4; j++) acc[i][j] = make_float2(0.f, 0.f);

    float4 av0 = *reinterpret_cast<const float4*>(Ag);
    float4 av1 = *reinterpret_cast<const float4*>(Ag + 4);
    float4 bv0 = *reinterpret_cast<const float4*>(Bg);
    float4 bv1 = *reinterpret_cast<const float4*>(Bg + 4);

    As[0][acb+0][arow] = av0.x; As[0][acb+1][arow] = av0.y;
    As[0][acb+2][arow] = av0.z; As[0][acb+3][arow] = av0.w;
    As[0][acb+4][arow] = av1.x; As[0][acb+5][arow] = av1.y;
    As[0][acb+6][arow] = av1.z; As[0][acb+7][arow] = av1.w;
    *reinterpret_cast<float4*>(&Bs[0][brow][bco])     = bv0;
    *reinterpret_cast<float4*>(&Bs[0][brow][bco + 4]) = bv1;
    __syncthreads();

    #pragma unroll 1
    for (int kt = 0; kt < 32; kt++) {
        const int buf = kt & 1;
        if (kt < 31) {
            const float* Agk = Ag + (kt + 1) * 16;
            av0 = *reinterpret_cast<const float4*>(Agk);
            av1 = *reinterpret_cast<const float4*>(Agk + 4);
            const float* Bgk = Bg + (size_t)(kt + 1) * 16 * H_;
            bv0 = *reinterpret_cast<const float4*>(Bgk);
            bv1 = *reinterpret_cast<const float4*>(Bgk + 4);
        }
        #pragma unroll
        for (int kk = 0; kk < 16; kk++) {
            float4 a0 = *reinterpret_cast<const float4*>(&As[buf][kk][mo]);
            float4 a1 = *reinterpret_cast<const float4*>(&As[buf][kk][mo + 4]);
            float4 b4 = *reinterpret_cast<const float4*>(&Bs[buf][kk][no]);
            float2 am[4] = {{a0.x,a0.y},{a0.z,a0.w},{a1.x,a1.y},{a1.z,a1.w}};
            float2 bd[4] = {{b4.x,b4.x},{b4.y,b4.y},{b4.z,b4.z},{b4.w,b4.w}};
            #pragma unroll
            for (int i = 0; i < 4; i++)
                #pragma unroll
                for (int j = 0; j < 4; j++)
                    fma2(acc[i][j], am[i], bd[j]);
        }
        if (kt < 31) {
            const int nb = buf ^ 1;
            As[nb][acb+0][arow] = av0.x; As[nb][acb+1][arow] = av0.y;
            As[nb][acb+2][arow] = av0.z; As[nb][acb+3][arow] = av0.w;
            As[nb][acb+4][arow] = av1.x; As[nb][acb+5][arow] = av1.y;
            As[nb][acb+6][arow] = av1.z; As[nb][acb+7][arow] = av1.w;
            *reinterpret_cast<float4*>(&Bs[nb][brow][bco])     = bv0;
            *reinterpret_cast<float4*>(&Bs[nb][brow][bco + 4]) = bv1;
        }
        __syncthreads();
    }

    float4 bb = make_float4(0.f, 0.f, 0.f, 0.f);
    if (relu) bb = *reinterpret_cast<const float4*>(&hb1[bcol + no]);
    #pragma unroll
    for (int i = 0; i < 4; i++) {
        const int r0 = m0 + mo + 2*i;
        float4 lo = make_float4(acc[i][0].x, acc[i][1].x, acc[i][2].x, acc[i][3].x);
        float4 hi = make_float4(acc[i][0].y, acc[i][1].y, acc[i][2].y, acc[i][3].y);
        if (relu) {
            lo.x = fmaxf(lo.x + bb.x, 0.f); lo.y = fmaxf(lo.y + bb.y, 0.f);
            lo.z = fmaxf(lo.z + bb.z, 0.f); lo.w = fmaxf(lo.w + bb.w, 0.f);
            hi.x = fmaxf(hi.x + bb.x, 0.f); hi.y = fmaxf(hi.y + bb.y, 0.f);
            hi.z = fmaxf(hi.z + bb.z, 0.f); hi.w = fmaxf(hi.w + bb.w, 0.f);
        }
        float* Cr = C + (size_t)r0 * 512 + n0 + no;
        *reinterpret_cast<float4*>(Cr)       = lo;
        *reinterpret_cast<float4*>(Cr + 512) = hi;
    }
}

// ---------------------------------------------------------------------------
// L2: bx<64 : hs[2048,128] = h1 @ hw2 + hb2      (64x64 tiles, K=256)
//     bx>=64: base[1152,256] = x0@w_x + preq[row/36] + b1  (64x64, K=128)
//     256 thr, double-buffered.
// ---------------------------------------------------------------------------
__global__ void __launch_bounds__(256) k2(
    const float* __restrict__ C, const float* __restrict__ hw2,
    const float* __restrict__ hb2, const float* __restrict__ x0,
    const float* __restrict__ w1, const float* __restrict__ b1,
    const float* __restrict__ preq,
    float* __restrict__ hs, float* __restrict__ base)
{
    __shared__ float As[2][16][68];
    __shared__ float Bs[2][16][64];
    const int tid = threadIdx.x;
    const int bx  = blockIdx.x;

    const float* A; const float* Bp; int lda, ldb, nt, m0, n0, mode;
    if (bx < 64) {
        mode = 0; const int tm = bx >> 1, tn = bx & 1;
        m0 = tm*64; n0 = tn*64;
        A = C + 256; lda = 512; Bp = hw2; ldb = 128; nt = 256/16;
    } else {
        mode = 1; const int bb = bx - 64; const int tm = bb >> 2, tn = bb & 3;
        m0 = tm*64; n0 = tn*64;
        A = x0; lda = 128; Bp = w1 + (size_t)DS_*H_; ldb = 256; nt = 128/16;
    }

    const int tx = tid & 15, ty = tid >> 4;
    const int ar = tid >> 2;
    const int ac = (tid & 3) << 2;
    const int bkr = tid >> 4;
    const int bn4 = (tid & 15) << 2;

    const float* Ag = A  + (size_t)(m0 + ar) * lda + ac;
    const float* Bg = Bp + (size_t)bkr * ldb + n0 + bn4;

    float2 acc[2][4];
    #pragma unroll
    for (int i = 0; i < 2; i++)
        #pragma unroll
        for (int j = 0; j < 4; j++) acc[i][j] = make_float2(0.f, 0.f);

    float4 av = *reinterpret_cast<const float4*>(Ag);
    float4 bv = *reinterpret_cast<const float4*>(Bg);
    As[0][ac+0][ar] = av.x; As[0][ac+1][ar] = av.y;
    As[0][ac+2][ar] = av.z; As[0][ac+3][ar] = av.w;
    *reinterpret_cast<float4*>(&Bs[0][bkr][bn4]) = bv;
    __syncthreads();

    #pragma unroll 1
    for (int kt = 0; kt < nt; kt++) {
        const int buf = kt & 1;
        if (kt + 1 < nt) {
            av = *reinterpret_cast<const float4*>(Ag + (kt+1)*16);
            bv = *reinterpret_cast<const float4*>(Bg + (size_t)(kt+1)*16*ldb);
        }
        #pragma unroll
        for (int kk = 0; kk < 16; kk++) {
            float4 a4 = *reinterpret_cast<const float4*>(&As[buf][kk][ty*4]);
            float4 b4 = *reinterpret_cast<const float4*>(&Bs[buf][kk][tx*4]);
            float2 a2v[2] = {{a4.x,a4.y},{a4.z,a4.w}};
            float2 bd[4]  = {{b4.x,b4.x},{b4.y,b4.y},{b4.z,b4.z},{b4.w,b4.w}};
            #pragma unroll
            for (int i = 0; i < 2; i++)
                #pragma unroll
                for (int j = 0; j < 4; j++)
                    fma2(acc[i][j], a2v[i], bd[j]);
        }
        if (kt + 1 < nt) {
            const int nb = buf ^ 1;
            As[nb][ac+0][ar] = av.x; As[nb][ac+1][ar] = av.y;
            As[nb][ac+2][ar] = av.z; As[nb][ac+3][ar] = av.w;
            *reinterpret_cast<float4*>(&Bs[nb][bkr][bn4]) = bv;
        }
        __syncthreads();
    }

    if (mode == 0) {
        float4 bb = *reinterpret_cast<const float4*>(&hb2[n0 + tx*4]);
        float* Or = hs + (size_t)(m0 + ty*4) * DX_ + n0 + tx*4;
        #pragma unroll
        for (int i = 0; i < 2; i++) {
            float4 lo = make_float4(acc[i][0].x+bb.x, acc[i][1].x+bb.y, acc[i][2].x+bb.z, acc[i][3].x+bb.w);
            float4 hi = make_float4(acc[i][0].y+bb.x, acc[i][1].y+bb.y, acc[i][2].y+bb.z, acc[i][3].y+bb.w);
            *reinterpret_cast<float4*>(Or + (size_t)(2*i  )*DX_) = lo;
            *reinterpret_cast<float4*>(Or + (size_t)(2*i+1)*DX_) = hi;
        }
    } else {
        float4 bb = *reinterpret_cast<const float4*>(&b1[n0 + tx*4]);
        #pragma unroll
        for (int i = 0; i < 2; i++) {
            const int r0 = m0 + ty*4 + 2*i;
            float4 p0 = *reinterpret_cast<const float4*>(&preq[(r0   /Kk_)*H_ + n0 + tx*4]);
            float4 p1 = *reinterpret_cast<const float4*>(&preq[((r0+1)/Kk_)*H_ + n0 + tx*4]);
            float4 lo = make_float4(acc[i][0].x+bb.x+p0.x, acc[i][1].x+bb.y+p0.y,
                                    acc[i][2].x+bb.z+p0.z, acc[i][3].x+bb.w+p0.w);
            float4 hi = make_float4(acc[i][0].y+bb.x+p1.x, acc[i][1].y+bb.y+p1.y,
                                    acc[i][2].y+bb.z+p1.z, acc[i][3].y+bb.w+p1.w);
            *reinterpret_cast<float4*>(&base[(size_t)(r0  )*H_ + n0 + tx*4]) = lo;
            *reinterpret_cast<float4*>(&base[(size_t)(r0+1)*H_ + n0 + tx*4]) = hi;
        }
    }
}

// ---------------------------------------------------------------------------
// L3: fused logits + softmax + aggregation + x0 copy. 4 k per block.
// ---------------------------------------------------------------------------
__global__ void __launch_bounds__(256) att_k(
    const float* __restrict__ Cmat, const float* __restrict__ base,
    const float* __restrict__ hsm, const float* __restrict__ w2,
    const float* __restrict__ x0, float* __restrict__ out)
{
    const int b  = blockIdx.x / 9;
    const int kg = blockIdx.x % 9;
    const int bk0 = b * Kk_ + kg * 4;
    const int tid = threadIdx.x;
    const int warp = tid >> 5, lane = tid & 31;

    __shared__ float base_s[4][H_];
    __shared__ float w2s[H_];
    __shared__ float lgt[4][M_];
    __shared__ float ew[4][M_];
    __shared__ float sinv[4];

    for (int idx = tid; idx < 4*H_; idx += 256)
        base_s[idx >> 8][idx & 255] = base[(size_t)(bk0 + (idx >> 8)) * H_ + (idx & 255)];
    w2s[tid] = w2[tid];
    __syncthreads();

    const float* pres = Cmat + (size_t)(b * M_) * 512;
    #pragma unroll
    for (int mi = 0; mi < 8; mi++) {
        const int m = warp * 8 + mi;
        const float* row = pres + (size_t)m * 512;
        float r[8];
        #pragma unroll
        for (int j = 0; j < 8; j++) r[j] = row[lane + 32*j];
        #pragma unroll
        for (int k = 0; k < 4; k++) {
            float acc = 0.f;
            #pragma unroll
            for (int j = 0; j < 8; j++) {
                const int h = lane + 32*j;
                acc = fmaf(fmaxf(r[j] + base_s[k][h], 0.f), w2s[h], acc);
            }
            #pragma unroll
            for (int off = 16; off; off >>= 1)
                acc += __shfl_xor_sync(0xffffffffu, acc, off);
            if (lane == 0) lgt[k][m] = acc;
        }
    }
    __syncthreads();

    if (warp < 4) {
        const int k = warp;
        float l0 = lgt[k][lane], l1 = lgt[k][lane + 32];
        float mx = fmaxf(l0, l1);
        #pragma unroll
        for (int off = 16; off; off >>= 1)
            mx = fmaxf(mx, __shfl_xor_sync(0xffffffffu, mx, off));
        float e0 = expf(l0 - mx), e1 = expf(l1 - mx);
        float s = e0 + e1;
        #pragma unroll
        for (int off = 16; off; off >>= 1)
            s += __shfl_xor_sync(0xffffffffu, s, off);
        ew[k][lane] = e0; ew[k][lane + 32] = e1;
        if (lane == 0) sinv[k] = 1.f / s;
    }
    __syncthreads();

    {
        const int f  = tid & 127;
        const int kp = tid >> 7;
        const int k0 = kp * 2, k1 = k0 + 1;
        const float* hb = hsm + (size_t)(b * M_) * DX_ + f;
        float a0 = 0.f, a1 = 0.f;
        #pragma unroll 8
        for (int m = 0; m < M_; m++) {
            const float v = hb[(size_t)m * DX_];
            a0 = fmaf(ew[k0][m], v, a0);
            a1 = fmaf(ew[k1][m], v, a1);
        }
        out[(size_t)(bk0 + k0) * 256 + 128 + f] = a0 * sinv[k0];
        out[(size_t)(bk0 + k1) * 256 + 128 + f] = a1 * sinv[k1];
    }
    for (int idx = tid; idx < 4 * DX_; idx += 256) {
        const int k = idx >> 7, f = idx & 127;
        out[(size_t)(bk0 + k) * 256 + f] = x0[(size_t)(bk0 + k) * DX_ + f];
    }
}

// ---------------------------------------------------------------------------
extern "C" void kernel_launch(void* const* d_in, const int* in_sizes, int n_in,
                              void* d_out, int out_size)
{
    (void)in_sizes; (void)n_in; (void)out_size;
    const float* s2  = (const float*)d_in[0];
    const float* x0  = (const float*)d_in[1];
    const float* q   = (const float*)d_in[2];
    const float* w1  = (const float*)d_in[3];
    const float* b1  = (const float*)d_in[4];
    const float* w2  = (const float*)d_in[5];
    const float* hw1 = (const float*)d_in[7];
    const float* hb1 = (const float*)d_in[8];
    const float* hw2 = (const float*)d_in[9];
    const float* hb2 = (const float*)d_in[10];
    float* out = (float*)d_out;

    float *preq, *C, *hs, *base;
    cudaGetSymbolAddress((void**)&preq, g_preq);
    cudaGetSymbolAddress((void**)&C,    g_C);
    cudaGetSymbolAddress((void**)&hs,   g_hs);
    cudaGetSymbolAddress((void**)&base, g_base);

    // L1: 256 GEMM tiles (64x64) + 32 preq blocks => ~2 blocks/SM, one wave
    k1<<<288, 128>>>(s2, w1, hw1, hb1, q, C, preq);
    // L2: hs (64 tiles) + base (72 tiles)
    k2<<<136, 256>>>(C, hw2, hb2, x0, w1, b1, preq, hs, base);
    // L3: fused attention + output
    att_k<<<288, 256>>>(C, base, hs, w2, x0, out);
}